// round 16
// baseline (speedup 1.0000x reference)
#include <cuda_runtime.h>
#include <cuda_fp16.h>
#include <cstdint>
#include <math.h>

#define N_NODES 2048
#define BATCH   64
#define D_IN    2
#define UNITS   64
#define F_IN    66            // D_IN + UNITS
#define NMAT    5             // num diffusion matrices
#define NNZ     65536
#define FB      (F_IN*BATCH)  // 4224 halves per node row
#define FBH2    (FB/2)        // 2112 half2 per row
#define FB16    (FB/8)        // 528 16B-groups per row
#define KTOT    (F_IN*NMAT)   // 330
#define KPAD    336           // padded to 21 k16 steps
#define NSLOT   6             // 5 diffusion slots + cand-x0 slot

// ---------------- scratch (static device globals; no runtime allocation) ----
__device__ __align__(16) __half g_x[NSLOT][(size_t)N_NODES*FB];  // 103.8 MB
__device__ float g_ru[(size_t)BATCH*N_NODES*2*UNITS];            // 67 MB (u half used)
__device__ __align__(16) __half g_whg[KPAD*2*UNITS];             // W_gate fp16, K-padded
__device__ __align__(16) __half g_whc[KPAD*UNITS];               // W_cand fp16, K-padded
__device__ int   g_cnt[2][N_NODES];     // zero at load; k_fill self-cleans per replay
__device__ int   g_off[2][N_NODES+1];
__device__ int   g_cur[2][N_NODES];
__device__ int   g_ccol[2][NNZ];
__device__ float g_cval[2][NNZ];

// ---------------- mega: edge count | convW (disjoint block ranges) ----------
__global__ void k_count_convW(const int* __restrict__ e1, const int* __restrict__ e2,
                              const float* __restrict__ Wg, const float* __restrict__ Wc) {
    int blk = blockIdx.x, tid = threadIdx.x;
    if (blk < 256) {
        int e = blk*256 + tid;
        if (e < NNZ) {
            atomicAdd(&g_cnt[0][e1[e]], 1);
            atomicAdd(&g_cnt[1][e2[e]], 1);
        }
    } else {
        int i = (blk - 256)*256 + tid;
        if (i < KPAD*2*UNITS) {
            int k = i >> 7, o = i & 127;
            g_whg[i] = __float2half(k < KTOT ? Wg[k*(2*UNITS) + o] : 0.f);
        }
        if (i < KPAD*UNITS) {
            int k = i >> 6, o = i & 63;
            g_whc[i] = __float2half(k < KTOT ? Wc[k*UNITS + o] : 0.f);
        }
    }
}

__global__ void k_scan() {
    int s = blockIdx.x;
    int lane = threadIdx.x;
    int base = lane * 64;
    int sum = 0;
    #pragma unroll 4
    for (int i = 0; i < 64; i++) sum += g_cnt[s][base+i];
    int pre = sum;
    #pragma unroll
    for (int d = 1; d < 32; d <<= 1) {
        int v = __shfl_up_sync(0xffffffffu, pre, d);
        if (lane >= d) pre += v;
    }
    int run = pre - sum;
    for (int i = 0; i < 64; i++) {
        g_off[s][base+i] = run;
        g_cur[s][base+i] = run;
        run += g_cnt[s][base+i];
    }
    if (lane == 31) g_off[s][N_NODES] = run;
}

__global__ void k_fill(const int* __restrict__ e1, const float* __restrict__ v1,
                       const int* __restrict__ e2, const float* __restrict__ v2) {
    int e = blockIdx.x*blockDim.x + threadIdx.x;
    if (e < NNZ) {
        int r = e1[e];
        int p = atomicAdd(&g_cur[0][r], 1);
        g_ccol[0][p] = e1[NNZ + e];
        g_cval[0][p] = v1[e];
        g_cnt[0][r] = 0;                 // self-clean for next graph replay
        r = e2[e];
        p = atomicAdd(&g_cur[1][r], 1);
        g_ccol[1][p] = e2[NNZ + e];
        g_cval[1][p] = v2[e];
        g_cnt[1][r] = 0;
    }
}

// ---------------- build x0 [N][F][B] (b fastest) in half (gate only) --------
__global__ void k_build_x0(const float* __restrict__ inputs,
                           const float* __restrict__ state) {
    __shared__ float tile[F_IN*65];
    int n = blockIdx.x, tid = threadIdx.x;

    for (int li = tid; li < BATCH*D_IN; li += blockDim.x) {
        int b = li >> 1, f = li & 1;
        tile[f*65 + b] = inputs[(size_t)b*(N_NODES*D_IN) + n*D_IN + f];
    }
    for (int li = tid; li < BATCH*UNITS; li += blockDim.x) {
        int b = li >> 6, j = li & 63;
        tile[(j + 2)*65 + b] = state[(size_t)b*((size_t)N_NODES*UNITS) + n*UNITS + j];
    }
    __syncthreads();
    __half2* dst = ((__half2*)g_x[0]) + (size_t)n*FBH2;
    for (int li = tid; li < FBH2; li += blockDim.x) {
        int f = li >> 5, b2 = li & 31;
        float2 v2 = make_float2(tile[f*65 + 2*b2], tile[f*65 + 2*b2 + 1]);
        dst[li] = __float22half2_rn(v2);
    }
}

// ---------------- SpMM: grouped HFMA2 accumulate (4 edges), fp32 outer sum --
__global__ void __launch_bounds__(528, 2) k_spmm(int hop2, int x0slot) {
    __shared__ int2 sdat[128];     // .x = col, .y = half2(v,v) bits

    int s = blockIdx.y;
    int iin  = hop2 ? 1 + 2*s : x0slot;
    int iout = hop2 ? 2 + 2*s : 1 + 2*s;

    const uint4* __restrict__ xin  = (const uint4*)g_x[iin];
    uint4* __restrict__       xout = (uint4*)g_x[iout];

    int n   = blockIdx.x;
    int idx = threadIdx.x;             // 0..527
    const uint4* __restrict__ xrow = xin + idx;
    int beg = g_off[s][n], end = g_off[s][n+1];

    float acc[8];
    #pragma unroll
    for (int i = 0; i < 8; i++) acc[i] = 0.f;

    for (int t = beg; t < end; t += 128) {
        int c = min(end - t, 128);
        __syncthreads();
        if (threadIdx.x < c) {
            int col = g_ccol[s][t + threadIdx.x];
            __half2 h2 = __half2half2(__float2half_rn(g_cval[s][t + threadIdx.x]));
            sdat[threadIdx.x] = make_int2(col, *(int*)&h2);
        }
        __syncthreads();

        int j0 = 0;
        for (; j0 + 4 <= c; j0 += 4) {
            __half2 p0 = __float2half2_rn(0.f), p1 = p0, p2 = p0, p3 = p0;
            #pragma unroll
            for (int jj = 0; jj < 4; jj++) {
                int2 d = sdat[j0 + jj];
                __half2 vh = *(__half2*)&d.y;
                uint4 raw = __ldg(xrow + (size_t)d.x*FB16);
                const __half2* h = (const __half2*)&raw;
                p0 = __hfma2(vh, h[0], p0);
                p1 = __hfma2(vh, h[1], p1);
                p2 = __hfma2(vh, h[2], p2);
                p3 = __hfma2(vh, h[3], p3);
            }
            float2 f;
            f = __half22float2(p0); acc[0] += f.x; acc[1] += f.y;
            f = __half22float2(p1); acc[2] += f.x; acc[3] += f.y;
            f = __half22float2(p2); acc[4] += f.x; acc[5] += f.y;
            f = __half22float2(p3); acc[6] += f.x; acc[7] += f.y;
        }
        if (j0 < c) {
            __half2 p0 = __float2half2_rn(0.f), p1 = p0, p2 = p0, p3 = p0;
            for (; j0 < c; j0++) {
                int2 d = sdat[j0];
                __half2 vh = *(__half2*)&d.y;
                uint4 raw = __ldg(xrow + (size_t)d.x*FB16);
                const __half2* h = (const __half2*)&raw;
                p0 = __hfma2(vh, h[0], p0);
                p1 = __hfma2(vh, h[1], p1);
                p2 = __hfma2(vh, h[2], p2);
                p3 = __hfma2(vh, h[3], p3);
            }
            float2 f;
            f = __half22float2(p0); acc[0] += f.x; acc[1] += f.y;
            f = __half22float2(p1); acc[2] += f.x; acc[3] += f.y;
            f = __half22float2(p2); acc[4] += f.x; acc[5] += f.y;
            f = __half22float2(p3); acc[6] += f.x; acc[7] += f.y;
        }
    }

    size_t o = (size_t)n*FB16 + idx;
    if (hop2) {
        uint4 raw = ((const uint4*)g_x[x0slot])[o];
        const __half2* h = (const __half2*)&raw;
        #pragma unroll
        for (int q = 0; q < 4; q++) {
            float2 f2 = __half22float2(h[q]);
            acc[2*q]   = 2.f*acc[2*q]   - f2.x;
            acc[2*q+1] = 2.f*acc[2*q+1] - f2.y;
        }
    }
    uint4 outv;
    __half2* ho = (__half2*)&outv;
    #pragma unroll
    for (int q = 0; q < 4; q++)
        ho[q] = __float22half2_rn(make_float2(acc[2*q], acc[2*q+1]));
    xout[o] = outv;
}

// ---------------- HMMA / cp.async helpers ----------------
__device__ __forceinline__ unsigned int smaddr(const void* p) {
    return (unsigned int)__cvta_generic_to_shared(p);
}

__device__ __forceinline__ void ldsm4_trans(unsigned int& r0, unsigned int& r1,
                                            unsigned int& r2, unsigned int& r3,
                                            unsigned int addr) {
    asm volatile("ldmatrix.sync.aligned.m8n8.x4.trans.shared.b16 {%0,%1,%2,%3}, [%4];"
                 : "=r"(r0), "=r"(r1), "=r"(r2), "=r"(r3) : "r"(addr));
}

__device__ __forceinline__ void mma16816(float* c,
                                         unsigned int a0, unsigned int a1,
                                         unsigned int a2, unsigned int a3,
                                         unsigned int b0, unsigned int b1) {
    asm volatile("mma.sync.aligned.m16n8k16.row.col.f32.f16.f16.f32 "
                 "{%0,%1,%2,%3}, {%4,%5,%6,%7}, {%8,%9}, {%0,%1,%2,%3};"
                 : "+f"(c[0]), "+f"(c[1]), "+f"(c[2]), "+f"(c[3])
                 : "r"(a0), "r"(a1), "r"(a2), "r"(a3), "r"(b0), "r"(b1));
}

__device__ __forceinline__ void cp16(void* dst, const void* src) {
    asm volatile("cp.async.cg.shared.global [%0], [%1], 16;"
                 :: "r"(smaddr(dst)), "l"(src));
}
__device__ __forceinline__ void cp_commit() {
    asm volatile("cp.async.commit_group;");
}
template<int NG> __device__ __forceinline__ void cp_wait() {
    asm volatile("cp.async.wait_group %0;" :: "n"(NG));
}

// ---------------- pipelined HMMA GEMM: 2 nodes/block, M=128, KC2=112 --------
// gate (FINAL=0): r half (warp_n==0) -> smem tile -> coalesced cand-x0 (slot 5);
//                 u half (warp_n==1) -> g_ru. cand (FINAL=1): GRU combine -> out.
template<int OUT, bool FINAL>
__global__ void __launch_bounds__(256) k_gemm_mma(const float* __restrict__ bias,
                                                  const float* __restrict__ state,
                                                  float* __restrict__ out) {
    const __half* __restrict__ Wh = FINAL ? g_whc : g_whg;
    constexpr int KC2 = 112, NCH = KPAD/KC2;    // 3 chunks
    constexpr int XS_STR = 136;                  // halves (272B rows, conflict-free)
    constexpr int WS_STR = OUT + 8;
    constexpr int NW8 = (OUT/2)/8;
    constexpr int WSEG = OUT/8;                  // 16B segs per W row
    constexpr int RT_STR = 72;                   // r-tile row stride (halves)

    extern __shared__ __align__(16) char dyn[];
    __half* A0 = (__half*)dyn;
    __half* A1 = A0 + KC2*XS_STR;
    __half* W0 = A1 + KC2*XS_STR;
    __half* W1 = W0 + KC2*WS_STR;
    __half* sxr = (__half*)dyn;                  // r tile reuses A0 (dead after loop)

    int n0 = blockIdx.x*2, tid = threadIdx.x;
    int warp = tid >> 5, lane = tid & 31;
    int warp_m = warp & 3, warp_n = warp >> 2;

    float acc[2][NW8][4];
    #pragma unroll
    for (int mt = 0; mt < 2; mt++)
        #pragma unroll
        for (int j = 0; j < NW8; j++)
            #pragma unroll
            for (int i = 0; i < 4; i++) acc[mt][j][i] = 0.f;

    auto load_chunk = [&](int kc, __half* xs, __half* ws) {
        for (int li = tid; li < KC2*16; li += 256) {
            int kl = li >> 4, sg = li & 15;
            int node = sg >> 3, b8 = sg & 7;
            int k = kc + kl;
            __half* dst = &xs[kl*XS_STR + node*64 + b8*8];
            if (k < KTOT) {
                int f = k / NMAT, m = k - f*NMAT;   // W row order: k = f*M + m
                int slot = (FINAL && m == 0) ? 5 : m;
                cp16(dst, g_x[slot] + (size_t)(n0 + node)*FB + f*64 + b8*8);
            } else {
                *(float4*)dst = make_float4(0.f, 0.f, 0.f, 0.f);
            }
        }
        for (int li = tid; li < KC2*WSEG; li += 256) {
            int kl = li / WSEG, sg = li - kl*WSEG;
            cp16(&ws[kl*WS_STR + sg*8], Wh + (size_t)(kc + kl)*OUT + sg*8);
        }
    };

    int r8   = lane & 7;
    int a_kh = (lane >> 4) & 1;
    int a_bh = (lane >> 3) & 1;
    int b_kh = (lane >> 3) & 1;
    int b_oh = lane >> 4;

    auto mma_chunk = [&](const __half* xs, const __half* ws) {
        #pragma unroll
        for (int kk = 0; kk < KC2/16; kk++) {
            unsigned int a[2][4];
            #pragma unroll
            for (int mt = 0; mt < 2; mt++)
                ldsm4_trans(a[mt][0], a[mt][1], a[mt][2], a[mt][3],
                    smaddr(&xs[(kk*16 + a_kh*8 + r8)*XS_STR + warp_m*32 + mt*16 + a_bh*8]));
            #pragma unroll
            for (int j = 0; j < NW8/2; j++) {
                unsigned int b0, b1, b2, b3;
                ldsm4_trans(b0, b1, b2, b3,
                    smaddr(&ws[(kk*16 + b_kh*8 + r8)*WS_STR + warp_n*(OUT/2) + j*16 + b_oh*8]));
                mma16816(acc[0][2*j],     a[0][0], a[0][1], a[0][2], a[0][3], b0, b1);
                mma16816(acc[0][2*j + 1], a[0][0], a[0][1], a[0][2], a[0][3], b2, b3);
                mma16816(acc[1][2*j],     a[1][0], a[1][1], a[1][2], a[1][3], b0, b1);
                mma16816(acc[1][2*j + 1], a[1][0], a[1][1], a[1][2], a[1][3], b2, b3);
            }
        }
    };

    load_chunk(0, A0, W0);
    cp_commit();
    for (int t = 0; t < NCH; t++) {
        const __half* xa = (t & 1) ? A1 : A0;
        const __half* wa = (t & 1) ? W1 : W0;
        __half* xn = (t & 1) ? A0 : A1;
        __half* wn = (t & 1) ? W0 : W1;
        if (t + 1 < NCH) {
            load_chunk((t + 1)*KC2, xn, wn);
            cp_commit();
            cp_wait<1>();
        } else {
            cp_wait<0>();
        }
        __syncthreads();
        mma_chunk(xa, wa);
        __syncthreads();
    }

    // ---- direct epilogue from accumulators ----
    int g = lane >> 2, t4 = lane & 3;
    #pragma unroll
    for (int mt = 0; mt < 2; mt++) {
        int r = warp_m*32 + mt*16 + g;       // rows r and r+8, same node
        int node = r >> 6;
        int b = r & 63;
        int n = n0 + node;
        #pragma unroll
        for (int j = 0; j < NW8; j++) {
            int o = warp_n*(OUT/2) + j*8 + t4*2;
            float2 bv = *(const float2*)&bias[o];
            if (!FINAL) {
                float v0 = 1.f/(1.f + __expf(-(acc[mt][j][0] + bv.x)));
                float v1 = 1.f/(1.f + __expf(-(acc[mt][j][1] + bv.y)));
                float v2 = 1.f/(1.f + __expf(-(acc[mt][j][2] + bv.x)));
                float v3 = 1.f/(1.f + __expf(-(acc[mt][j][3] + bv.y)));
                if (warp_n == 0) {
                    // r: multiply by state, stage into smem tile [o][b] (stride 72)
                    size_t si = (size_t)b*((size_t)N_NODES*UNITS) + n*UNITS + o;
                    float2 st0 = *(const float2*)&state[si];
                    float2 st1 = *(const float2*)&state[si + 8*((size_t)N_NODES*UNITS)];
                    __half* tb = sxr + node*(UNITS*RT_STR);
                    tb[o*RT_STR + b]           = __float2half(v0*st0.x);
                    tb[(o+1)*RT_STR + b]       = __float2half(v1*st0.y);
                    tb[o*RT_STR + b + 8]       = __float2half(v2*st1.x);
                    tb[(o+1)*RT_STR + b + 8]   = __float2half(v3*st1.y);
                } else {
                    int ou = o - UNITS + UNITS;  // o already >= 64; keep absolute
                    *(float2*)&g_ru[((size_t)b*N_NODES + n)*OUT + ou] = make_float2(v0, v1);
                    *(float2*)&g_ru[((size_t)(b + 8)*N_NODES + n)*OUT + ou] = make_float2(v2, v3);
                }
            } else {
                {
                    float c0 = tanhf(acc[mt][j][0] + bv.x);
                    float c1 = tanhf(acc[mt][j][1] + bv.y);
                    float2 u = *(const float2*)&g_ru[((size_t)b*N_NODES + n)*(2*UNITS) + UNITS + o];
                    size_t gi = (size_t)b*((size_t)N_NODES*UNITS) + n*UNITS + o;
                    float2 st = *(const float2*)&state[gi];
                    *(float2*)&out[gi] = make_float2(u.x*st.x + (1.f - u.x)*c0,
                                                     u.y*st.y + (1.f - u.y)*c1);
                }
                {
                    float c0 = tanhf(acc[mt][j][2] + bv.x);
                    float c1 = tanhf(acc[mt][j][3] + bv.y);
                    int b2 = b + 8;
                    float2 u = *(const float2*)&g_ru[((size_t)b2*N_NODES + n)*(2*UNITS) + UNITS + o];
                    size_t gi = (size_t)b2*((size_t)N_NODES*UNITS) + n*UNITS + o;
                    float2 st = *(const float2*)&state[gi];
                    *(float2*)&out[gi] = make_float2(u.x*st.x + (1.f - u.x)*c0,
                                                     u.y*st.y + (1.f - u.y)*c1);
                }
            }
        }
    }

    if (!FINAL) {
        __syncthreads();
        // coalesced copy: r tile -> cand x0 state features (f = 2..65)
        // 2 nodes x 64 f-rows x 8 uint4 groups = 1024 uint4
        for (int li = tid; li < 2*UNITS*8; li += 256) {
            int node = li >> 9, rem = li & 511;
            int f = rem >> 3, b8 = rem & 7;
            uint4 v = *(const uint4*)&sxr[node*(UNITS*RT_STR) + f*RT_STR + b8*8];
            *(uint4*)&g_x[5][(size_t)(n0 + node)*FB + (f + 2)*64 + b8*8] = v;
        }
        // copy the 2 input features (first 128 halves per node) from gate x0
        for (int li = tid; li < 2*16; li += 256) {
            int node = li >> 4, q = li & 15;
            *(uint4*)&g_x[5][(size_t)(n0 + node)*FB + q*8] =
                *(const uint4*)&g_x[0][(size_t)(n0 + node)*FB + q*8];
        }
    }
}

// ---------------- launch ----------------
extern "C" void kernel_launch(void* const* d_in, const int* in_sizes, int n_in,
                              void* d_out, int out_size) {
    const float* inputs = (const float*)d_in[0];
    const float* state  = (const float*)d_in[1];
    const int*   e1     = (const int*)  d_in[2];
    const float* v1     = (const float*)d_in[3];
    const int*   e2     = (const int*)  d_in[4];
    const float* v2     = (const float*)d_in[5];
    const float* Wg     = (const float*)d_in[6];
    const float* bg     = (const float*)d_in[7];
    const float* Wc     = (const float*)d_in[8];
    const float* bc     = (const float*)d_in[9];
    float* out = (float*)d_out;

    const int smg = 2*112*(136 + 136)*2;   // 121856 B (gate)
    const int smc = 2*112*(136 + 72)*2;    //  93184 B (cand)
    cudaFuncSetAttribute(k_gemm_mma<2*UNITS, false>,
                         cudaFuncAttributeMaxDynamicSharedMemorySize, smg);
    cudaFuncSetAttribute(k_gemm_mma<UNITS, true>,
                         cudaFuncAttributeMaxDynamicSharedMemorySize, smc);

    k_count_convW<<<256 + 168, 256>>>(e1, e2, Wg, Wc);
    k_scan<<<2, 32>>>();
    k_fill<<<NNZ/256, 256>>>(e1, v1, e2, v2);

    dim3 sgrid(N_NODES, 2);

    // ---- gate dconv ----
    k_build_x0<<<N_NODES, 256>>>(inputs, state);
    k_spmm<<<sgrid, 528>>>(0, 0);
    k_spmm<<<sgrid, 528>>>(1, 0);
    k_gemm_mma<2*UNITS, false><<<N_NODES/2, 256, smg>>>(bg, state, (float*)0);

    // ---- candidate dconv (x0 = slot 5, built by gate epilogue) ----
    k_spmm<<<sgrid, 528>>>(0, 5);
    k_spmm<<<sgrid, 528>>>(1, 5);
    k_gemm_mma<UNITS, true><<<N_NODES/2, 256, smc>>>(bc, state, out);
}

// round 17
// speedup vs baseline: 1.0440x; 1.0440x over previous
#include <cuda_runtime.h>
#include <cuda_fp16.h>
#include <cstdint>
#include <math.h>

#define N_NODES 2048
#define BATCH   64
#define D_IN    2
#define UNITS   64
#define F_IN    66            // D_IN + UNITS
#define NMAT    5             // num diffusion matrices
#define NNZ     65536
#define FB      (F_IN*BATCH)  // 4224 halves per node row
#define FBH2    (FB/2)        // 2112 half2 per row
#define FB16    (FB/8)        // 528 16B-groups per row
#define KTOT    (F_IN*NMAT)   // 330
#define KPAD    336           // padded to 21 k16 steps

// ---------------- scratch (static device globals; no runtime allocation) ----
__device__ __align__(16) __half g_x[NMAT][(size_t)N_NODES*FB];   // 86.5 MB
__device__ float g_ru[(size_t)BATCH*N_NODES*2*UNITS];            // 67 MB
__device__ __align__(16) __half g_whg[KPAD*2*UNITS];             // W_gate fp16, K-padded
__device__ __align__(16) __half g_whc[KPAD*UNITS];               // W_cand fp16, K-padded
__device__ int   g_cnt[2][N_NODES];
__device__ int   g_off[2][N_NODES+1];
__device__ int   g_cur[2][N_NODES];
__device__ int   g_ccol[2][NNZ];
__device__ float g_cval[2][NNZ];

// ---------------- CSR build ----------------
__global__ void k_zero() {
    int i = blockIdx.x*blockDim.x + threadIdx.x;
    if (i < 2*N_NODES) ((int*)g_cnt)[i] = 0;
}

__global__ void k_count(const int* __restrict__ e1, const int* __restrict__ e2) {
    int e = blockIdx.x*blockDim.x + threadIdx.x;
    if (e < NNZ) {
        atomicAdd(&g_cnt[0][e1[e]], 1);
        atomicAdd(&g_cnt[1][e2[e]], 1);
    }
}

__global__ void k_scan() {
    int s = blockIdx.x;
    int lane = threadIdx.x;
    int base = lane * 64;
    int sum = 0;
    #pragma unroll 4
    for (int i = 0; i < 64; i++) sum += g_cnt[s][base+i];
    int pre = sum;
    #pragma unroll
    for (int d = 1; d < 32; d <<= 1) {
        int v = __shfl_up_sync(0xffffffffu, pre, d);
        if (lane >= d) pre += v;
    }
    int run = pre - sum;
    for (int i = 0; i < 64; i++) {
        g_off[s][base+i] = run;
        g_cur[s][base+i] = run;
        run += g_cnt[s][base+i];
    }
    if (lane == 31) g_off[s][N_NODES] = run;
}

__global__ void k_fill(const int* __restrict__ e1, const float* __restrict__ v1,
                       const int* __restrict__ e2, const float* __restrict__ v2) {
    int e = blockIdx.x*blockDim.x + threadIdx.x;
    if (e < NNZ) {
        int r = e1[e];
        int p = atomicAdd(&g_cur[0][r], 1);
        g_ccol[0][p] = e1[NNZ + e];
        g_cval[0][p] = v1[e];
        r = e2[e];
        p = atomicAdd(&g_cur[1][r], 1);
        g_ccol[1][p] = e2[NNZ + e];
        g_cval[1][p] = v2[e];
    }
}

// ---------------- W fp32 -> fp16 with K zero-padding ----------------
__global__ void k_convW(const float* __restrict__ Wg, const float* __restrict__ Wc) {
    int i = blockIdx.x*blockDim.x + threadIdx.x;
    if (i < KPAD*2*UNITS) {
        int k = i >> 7, o = i & 127;
        g_whg[i] = __float2half(k < KTOT ? Wg[k*(2*UNITS) + o] : 0.f);
    }
    if (i < KPAD*UNITS) {
        int k = i >> 6, o = i & 63;
        g_whc[i] = __float2half(k < KTOT ? Wc[k*UNITS + o] : 0.f);
    }
}

// ---------------- build x0 [N][F][B] (b fastest) in half, optionally state*r --
__global__ void k_build_x0(const float* __restrict__ inputs,
                           const float* __restrict__ state,
                           int use_r) {
    __shared__ float tile[F_IN*65];
    int n = blockIdx.x, tid = threadIdx.x;

    for (int li = tid; li < BATCH*D_IN; li += blockDim.x) {
        int b = li >> 1, f = li & 1;
        tile[f*65 + b] = inputs[(size_t)b*(N_NODES*D_IN) + n*D_IN + f];
    }
    for (int li = tid; li < BATCH*UNITS; li += blockDim.x) {
        int b = li >> 6, j = li & 63;
        float v = state[(size_t)b*((size_t)N_NODES*UNITS) + n*UNITS + j];
        if (use_r) v *= g_ru[((size_t)b*N_NODES + n)*(2*UNITS) + j];
        tile[(j + 2)*65 + b] = v;
    }
    __syncthreads();
    __half2* dst = ((__half2*)g_x[0]) + (size_t)n*FBH2;
    for (int li = tid; li < FBH2; li += blockDim.x) {
        int f = li >> 5, b2 = li & 31;
        float2 v2 = make_float2(tile[f*65 + 2*b2], tile[f*65 + 2*b2 + 1]);
        dst[li] = __float22half2_rn(v2);
    }
}

// ---------------- SpMM: grouped HFMA2 accumulate (4 edges), fp32 outer sum --
// grid (N_NODES, 2): y = support. block 528 threads (one node row, 8 halves each)
__global__ void __launch_bounds__(528, 2) k_spmm(int hop2) {
    __shared__ int2 sdat[128];     // .x = col, .y = half2(v,v) bits

    int s = blockIdx.y;
    int iin  = hop2 ? 1 + 2*s : 0;
    int iout = hop2 ? 2 + 2*s : 1 + 2*s;

    const uint4* __restrict__ xin  = (const uint4*)g_x[iin];
    uint4* __restrict__       xout = (uint4*)g_x[iout];

    int n   = blockIdx.x;
    int idx = threadIdx.x;             // 0..527
    const uint4* __restrict__ xrow = xin + idx;
    int beg = g_off[s][n], end = g_off[s][n+1];

    float acc[8];
    #pragma unroll
    for (int i = 0; i < 8; i++) acc[i] = 0.f;

    for (int t = beg; t < end; t += 128) {
        int c = min(end - t, 128);
        __syncthreads();
        if (threadIdx.x < c) {
            int col = g_ccol[s][t + threadIdx.x];
            __half2 h2 = __half2half2(__float2half_rn(g_cval[s][t + threadIdx.x]));
            sdat[threadIdx.x] = make_int2(col, *(int*)&h2);
        }
        __syncthreads();

        int j0 = 0;
        for (; j0 + 4 <= c; j0 += 4) {
            __half2 p0 = __float2half2_rn(0.f), p1 = p0, p2 = p0, p3 = p0;
            #pragma unroll
            for (int jj = 0; jj < 4; jj++) {
                int2 d = sdat[j0 + jj];
                __half2 vh = *(__half2*)&d.y;
                uint4 raw = __ldg(xrow + (size_t)d.x*FB16);
                const __half2* h = (const __half2*)&raw;
                p0 = __hfma2(vh, h[0], p0);
                p1 = __hfma2(vh, h[1], p1);
                p2 = __hfma2(vh, h[2], p2);
                p3 = __hfma2(vh, h[3], p3);
            }
            float2 f;
            f = __half22float2(p0); acc[0] += f.x; acc[1] += f.y;
            f = __half22float2(p1); acc[2] += f.x; acc[3] += f.y;
            f = __half22float2(p2); acc[4] += f.x; acc[5] += f.y;
            f = __half22float2(p3); acc[6] += f.x; acc[7] += f.y;
        }
        if (j0 < c) {
            __half2 p0 = __float2half2_rn(0.f), p1 = p0, p2 = p0, p3 = p0;
            for (; j0 < c; j0++) {
                int2 d = sdat[j0];
                __half2 vh = *(__half2*)&d.y;
                uint4 raw = __ldg(xrow + (size_t)d.x*FB16);
                const __half2* h = (const __half2*)&raw;
                p0 = __hfma2(vh, h[0], p0);
                p1 = __hfma2(vh, h[1], p1);
                p2 = __hfma2(vh, h[2], p2);
                p3 = __hfma2(vh, h[3], p3);
            }
            float2 f;
            f = __half22float2(p0); acc[0] += f.x; acc[1] += f.y;
            f = __half22float2(p1); acc[2] += f.x; acc[3] += f.y;
            f = __half22float2(p2); acc[4] += f.x; acc[5] += f.y;
            f = __half22float2(p3); acc[6] += f.x; acc[7] += f.y;
        }
    }

    size_t o = (size_t)n*FB16 + idx;
    if (hop2) {
        uint4 raw = ((const uint4*)g_x[0])[o];
        const __half2* h = (const __half2*)&raw;
        #pragma unroll
        for (int q = 0; q < 4; q++) {
            float2 f2 = __half22float2(h[q]);
            acc[2*q]   = 2.f*acc[2*q]   - f2.x;
            acc[2*q+1] = 2.f*acc[2*q+1] - f2.y;
        }
    }
    uint4 outv;
    __half2* ho = (__half2*)&outv;
    #pragma unroll
    for (int q = 0; q < 4; q++)
        ho[q] = __float22half2_rn(make_float2(acc[2*q], acc[2*q+1]));
    xout[o] = outv;
}

// ---------------- HMMA / cp.async helpers ----------------
__device__ __forceinline__ unsigned int smaddr(const void* p) {
    return (unsigned int)__cvta_generic_to_shared(p);
}

__device__ __forceinline__ void ldsm4_trans(unsigned int& r0, unsigned int& r1,
                                            unsigned int& r2, unsigned int& r3,
                                            unsigned int addr) {
    asm volatile("ldmatrix.sync.aligned.m8n8.x4.trans.shared.b16 {%0,%1,%2,%3}, [%4];"
                 : "=r"(r0), "=r"(r1), "=r"(r2), "=r"(r3) : "r"(addr));
}

__device__ __forceinline__ void mma16816(float* c,
                                         unsigned int a0, unsigned int a1,
                                         unsigned int a2, unsigned int a3,
                                         unsigned int b0, unsigned int b1) {
    asm volatile("mma.sync.aligned.m16n8k16.row.col.f32.f16.f16.f32 "
                 "{%0,%1,%2,%3}, {%4,%5,%6,%7}, {%8,%9}, {%0,%1,%2,%3};"
                 : "+f"(c[0]), "+f"(c[1]), "+f"(c[2]), "+f"(c[3])
                 : "r"(a0), "r"(a1), "r"(a2), "r"(a3), "r"(b0), "r"(b1));
}

__device__ __forceinline__ void cp16(void* dst, const void* src) {
    asm volatile("cp.async.cg.shared.global [%0], [%1], 16;"
                 :: "r"(smaddr(dst)), "l"(src));
}
__device__ __forceinline__ void cp_commit() {
    asm volatile("cp.async.commit_group;");
}
template<int NG> __device__ __forceinline__ void cp_wait() {
    asm volatile("cp.async.wait_group %0;" :: "n"(NG));
}

// ---------------- pipelined HMMA GEMM: 2 nodes/block, M=128, KC2=112 --------
// 8 warps: warp_m = warp&3 (32 rows each), warp_n = warp>>2 (OUT/2 cols each).
// cp.async double-buffered K-chunks of 112; direct register epilogue.
template<int OUT, bool FINAL>
__global__ void __launch_bounds__(256) k_gemm_mma(const float* __restrict__ bias,
                                                  const float* __restrict__ state,
                                                  float* __restrict__ out) {
    const __half* __restrict__ Wh = FINAL ? g_whc : g_whg;
    constexpr int KC2 = 112, NCH = KPAD/KC2;    // 3 chunks
    constexpr int XS_STR = 136;                  // halves (272B rows, conflict-free)
    constexpr int WS_STR = OUT + 8;
    constexpr int NW8 = (OUT/2)/8;
    constexpr int WSEG = OUT/8;                  // 16B segs per W row

    extern __shared__ __align__(16) char dyn[];
    __half* A0 = (__half*)dyn;
    __half* A1 = A0 + KC2*XS_STR;
    __half* W0 = A1 + KC2*XS_STR;
    __half* W1 = W0 + KC2*WS_STR;

    int n0 = blockIdx.x*2, tid = threadIdx.x;
    int warp = tid >> 5, lane = tid & 31;
    int warp_m = warp & 3, warp_n = warp >> 2;

    float acc[2][NW8][4];
    #pragma unroll
    for (int mt = 0; mt < 2; mt++)
        #pragma unroll
        for (int j = 0; j < NW8; j++)
            #pragma unroll
            for (int i = 0; i < 4; i++) acc[mt][j][i] = 0.f;

    auto load_chunk = [&](int kc, __half* xs, __half* ws) {
        for (int li = tid; li < KC2*16; li += 256) {
            int kl = li >> 4, sg = li & 15;
            int node = sg >> 3, b8 = sg & 7;
            int k = kc + kl;
            __half* dst = &xs[kl*XS_STR + node*64 + b8*8];
            if (k < KTOT) {
                int f = k / NMAT, m = k - f*NMAT;   // W row order: k = f*M + m
                cp16(dst, g_x[m] + (size_t)(n0 + node)*FB + f*64 + b8*8);
            } else {
                *(float4*)dst = make_float4(0.f, 0.f, 0.f, 0.f);
            }
        }
        for (int li = tid; li < KC2*WSEG; li += 256) {
            int kl = li / WSEG, sg = li - kl*WSEG;
            cp16(&ws[kl*WS_STR + sg*8], Wh + (size_t)(kc + kl)*OUT + sg*8);
        }
    };

    int r8   = lane & 7;
    int a_kh = (lane >> 4) & 1;
    int a_bh = (lane >> 3) & 1;
    int b_kh = (lane >> 3) & 1;
    int b_oh = lane >> 4;

    auto mma_chunk = [&](const __half* xs, const __half* ws) {
        #pragma unroll
        for (int kk = 0; kk < KC2/16; kk++) {
            unsigned int a[2][4];
            #pragma unroll
            for (int mt = 0; mt < 2; mt++)
                ldsm4_trans(a[mt][0], a[mt][1], a[mt][2], a[mt][3],
                    smaddr(&xs[(kk*16 + a_kh*8 + r8)*XS_STR + warp_m*32 + mt*16 + a_bh*8]));
            #pragma unroll
            for (int j = 0; j < NW8/2; j++) {
                unsigned int b0, b1, b2, b3;
                ldsm4_trans(b0, b1, b2, b3,
                    smaddr(&ws[(kk*16 + b_kh*8 + r8)*WS_STR + warp_n*(OUT/2) + j*16 + b_oh*8]));
                mma16816(acc[0][2*j],     a[0][0], a[0][1], a[0][2], a[0][3], b0, b1);
                mma16816(acc[0][2*j + 1], a[0][0], a[0][1], a[0][2], a[0][3], b2, b3);
                mma16816(acc[1][2*j],     a[1][0], a[1][1], a[1][2], a[1][3], b0, b1);
                mma16816(acc[1][2*j + 1], a[1][0], a[1][1], a[1][2], a[1][3], b2, b3);
            }
        }
    };

    load_chunk(0, A0, W0);
    cp_commit();
    for (int t = 0; t < NCH; t++) {
        const __half* xa = (t & 1) ? A1 : A0;
        const __half* wa = (t & 1) ? W1 : W0;
        __half* xn = (t & 1) ? A0 : A1;
        __half* wn = (t & 1) ? W0 : W1;
        if (t + 1 < NCH) {
            load_chunk((t + 1)*KC2, xn, wn);
            cp_commit();
            cp_wait<1>();
        } else {
            cp_wait<0>();
        }
        __syncthreads();
        mma_chunk(xa, wa);
        __syncthreads();
    }

    // ---- direct epilogue from accumulators ----
    int g = lane >> 2, t4 = lane & 3;
    #pragma unroll
    for (int mt = 0; mt < 2; mt++) {
        int r = warp_m*32 + mt*16 + g;       // rows r and r+8, same node
        int node = r >> 6;
        int b = r & 63;
        int n = n0 + node;
        #pragma unroll
        for (int j = 0; j < NW8; j++) {
            int o = warp_n*(OUT/2) + j*8 + t4*2;
            float2 bv = *(const float2*)&bias[o];
            if (!FINAL) {
                float v0 = 1.f/(1.f + __expf(-(acc[mt][j][0] + bv.x)));
                float v1 = 1.f/(1.f + __expf(-(acc[mt][j][1] + bv.y)));
                *(float2*)&g_ru[((size_t)b*N_NODES + n)*OUT + o] = make_float2(v0, v1);
                float v2 = 1.f/(1.f + __expf(-(acc[mt][j][2] + bv.x)));
                float v3 = 1.f/(1.f + __expf(-(acc[mt][j][3] + bv.y)));
                *(float2*)&g_ru[((size_t)(b + 8)*N_NODES + n)*OUT + o] = make_float2(v2, v3);
            } else {
                {
                    float c0 = tanhf(acc[mt][j][0] + bv.x);
                    float c1 = tanhf(acc[mt][j][1] + bv.y);
                    float2 u = *(const float2*)&g_ru[((size_t)b*N_NODES + n)*(2*UNITS) + UNITS + o];
                    size_t gi = (size_t)b*((size_t)N_NODES*UNITS) + n*UNITS + o;
                    float2 st = *(const float2*)&state[gi];
                    *(float2*)&out[gi] = make_float2(u.x*st.x + (1.f - u.x)*c0,
                                                     u.y*st.y + (1.f - u.y)*c1);
                }
                {
                    float c0 = tanhf(acc[mt][j][2] + bv.x);
                    float c1 = tanhf(acc[mt][j][3] + bv.y);
                    int b2 = b + 8;
                    float2 u = *(const float2*)&g_ru[((size_t)b2*N_NODES + n)*(2*UNITS) + UNITS + o];
                    size_t gi = (size_t)b2*((size_t)N_NODES*UNITS) + n*UNITS + o;
                    float2 st = *(const float2*)&state[gi];
                    *(float2*)&out[gi] = make_float2(u.x*st.x + (1.f - u.x)*c0,
                                                     u.y*st.y + (1.f - u.y)*c1);
                }
            }
        }
    }
}

// ---------------- launch ----------------
extern "C" void kernel_launch(void* const* d_in, const int* in_sizes, int n_in,
                              void* d_out, int out_size) {
    const float* inputs = (const float*)d_in[0];
    const float* state  = (const float*)d_in[1];
    const int*   e1     = (const int*)  d_in[2];
    const float* v1     = (const float*)d_in[3];
    const int*   e2     = (const int*)  d_in[4];
    const float* v2     = (const float*)d_in[5];
    const float* Wg     = (const float*)d_in[6];
    const float* bg     = (const float*)d_in[7];
    const float* Wc     = (const float*)d_in[8];
    const float* bc     = (const float*)d_in[9];
    float* out = (float*)d_out;

    const int smg = 2*112*(136 + 136)*2;   // 121856 B (gate)
    const int smc = 2*112*(136 + 72)*2;    //  93184 B (cand)
    cudaFuncSetAttribute(k_gemm_mma<2*UNITS, false>,
                         cudaFuncAttributeMaxDynamicSharedMemorySize, smg);
    cudaFuncSetAttribute(k_gemm_mma<UNITS, true>,
                         cudaFuncAttributeMaxDynamicSharedMemorySize, smc);

    k_zero <<<16, 256>>>();
    k_count<<<NNZ/256, 256>>>(e1, e2);
    k_scan <<<2, 32>>>();
    k_fill <<<NNZ/256, 256>>>(e1, v1, e2, v2);
    k_convW<<<(KPAD*2*UNITS + 255)/256, 256>>>(Wg, Wc);

    dim3 sgrid(N_NODES, 2);

    // ---- gate dconv ----
    k_build_x0<<<N_NODES, 256>>>(inputs, state, 0);
    k_spmm<<<sgrid, 528>>>(0);
    k_spmm<<<sgrid, 528>>>(1);
    k_gemm_mma<2*UNITS, false><<<N_NODES/2, 256, smg>>>(bg, (const float*)0, (float*)0);

    // ---- candidate dconv (state -> r*state) ----
    k_build_x0<<<N_NODES, 256>>>(inputs, state, 1);
    k_spmm<<<sgrid, 528>>>(0);
    k_spmm<<<sgrid, 528>>>(1);
    k_gemm_mma<UNITS, true><<<N_NODES/2, 256, smc>>>(bc, state, out);
}